// round 6
// baseline (speedup 1.0000x reference)
#include <cuda_runtime.h>
#include <cuda_bf16.h>
#include <cstdint>

#define NB   4
#define CIN  512
#define HWD  16384
#define KCL  19
#define KC   256
#define OUTC 512

#define BM 128
#define BN 128
#define BK 32
#define NS 3

typedef unsigned long long u64;
typedef unsigned int u32;

// ---------------- packed f32x2 helpers ----------------
__device__ __forceinline__ u64 pk2(float lo, float hi) {
    u64 r; asm("mov.b64 %0, {%1, %2};" : "=l"(r) : "f"(lo), "f"(hi)); return r;
}
__device__ __forceinline__ void ffma2(u64& d, u64 a, u64 b) {
    asm("fma.rn.f32x2 %0, %1, %2, %0;" : "+l"(d) : "l"(a), "l"(b));
}
__device__ __forceinline__ void fadd2(u64& d, u64 a) {
    asm("add.rn.f32x2 %0, %0, %1;" : "+l"(d) : "l"(a));
}
__device__ __forceinline__ float2 upk(u64 v) {
    float2 f; asm("mov.b64 {%0, %1}, %2;" : "=f"(f.x), "=f"(f.y) : "l"(v)); return f;
}
__device__ __forceinline__ void split_bf16(float v, __nv_bfloat16& h, __nv_bfloat16& l) {
    h = __float2bfloat16(v);
    l = __float2bfloat16(v - __bfloat162float(h));
}
__device__ __forceinline__ u32 pack_bf2(__nv_bfloat16 a, __nv_bfloat16 b) {
    __nv_bfloat162 t; t.x = a; t.y = b;
    return *reinterpret_cast<u32*>(&t);
}

// ---------------- mma / async helpers ----------------
__device__ __forceinline__ u32 smem_u32(const void* p) {
    u32 a;
    asm("{ .reg .u64 t; cvta.to.shared.u64 t, %1; cvt.u32.u64 %0, t; }" : "=r"(a) : "l"(p));
    return a;
}
__device__ __forceinline__ void ldsm4(u32* r, u32 addr) {
    asm volatile("ldmatrix.sync.aligned.m8n8.x4.shared.b16 {%0,%1,%2,%3}, [%4];\n"
        : "=r"(r[0]), "=r"(r[1]), "=r"(r[2]), "=r"(r[3]) : "r"(addr));
}
__device__ __forceinline__ void ldsm4t(u32* r, u32 addr) {
    asm volatile("ldmatrix.sync.aligned.m8n8.x4.trans.shared.b16 {%0,%1,%2,%3}, [%4];\n"
        : "=r"(r[0]), "=r"(r[1]), "=r"(r[2]), "=r"(r[3]) : "r"(addr));
}
__device__ __forceinline__ void mma16816(float* d, const u32* a, const u32* b) {
    asm volatile(
        "mma.sync.aligned.m16n8k16.row.col.f32.bf16.bf16.f32 "
        "{%0,%1,%2,%3}, {%4,%5,%6,%7}, {%8,%9}, {%0,%1,%2,%3};\n"
        : "+f"(d[0]), "+f"(d[1]), "+f"(d[2]), "+f"(d[3])
        : "r"(a[0]), "r"(a[1]), "r"(a[2]), "r"(a[3]), "r"(b[0]), "r"(b[1]));
}
__device__ __forceinline__ void cp16(u32 dst, const void* src) {
    asm volatile("cp.async.cg.shared.global [%0], [%1], 16;" :: "r"(dst), "l"(src) : "memory");
}
#define CP_COMMIT() asm volatile("cp.async.commit_group;" ::: "memory")
#define CP_WAIT1()  asm volatile("cp.async.wait_group 1;" ::: "memory")

// ---------------- scratch (device globals, zero-initialized) ----------------
__device__ float g_p[NB * KCL * HWD];
__device__ float g_proxy[NB * CIN * 20];
__device__ float g_t1[NB * KC * 20];
__device__ float g_kk[NB * KC * 20];
__device__ float g_val[NB * KC * 20];
__device__ float g_wv[NB * OUTC * 20];
__device__ float g_q2[(size_t)NB * KC * HWD];

// split bf16 activation planes: [n][hi plane | lo plane]
__device__ __nv_bfloat16 g_feats2[(size_t)NB * 2 * CIN * HWD];
__device__ __nv_bfloat16 g_q12[(size_t)NB * 2 * KC * HWD];
__device__ __nv_bfloat16 g_up2[(size_t)NB * 2 * CIN * HWD];

// split weights: [hi M*K][lo M*K] bf16
__device__ __nv_bfloat16 g_wp1_2[2 * (size_t)KC * CIN];
__device__ __nv_bfloat16 g_wp2_2[2 * (size_t)KC * KC];
__device__ __nv_bfloat16 g_wf_2[2 * (size_t)OUTC * 2 * CIN];

// ==================== spatial softmax per (n,k) ====================
__global__ __launch_bounds__(256) void softmax_k(const float* __restrict__ probs) {
    const int row = blockIdx.x;
    const float* x = probs + (size_t)row * HWD;
    float* y = g_p + (size_t)row * HWD;
    __shared__ float red[8];
    const int tid = threadIdx.x, lane = tid & 31, warp = tid >> 5;

    float m = -3.4e38f;
    for (int i = tid; i < HWD; i += 256) m = fmaxf(m, x[i]);
    #pragma unroll
    for (int s = 16; s; s >>= 1) m = fmaxf(m, __shfl_xor_sync(0xffffffffu, m, s));
    if (!lane) red[warp] = m;
    __syncthreads();
    m = red[0];
    #pragma unroll
    for (int w = 1; w < 8; w++) m = fmaxf(m, red[w]);

    float sum = 0.f;
    for (int i = tid; i < HWD; i += 256) sum += __expf(x[i] - m);
    #pragma unroll
    for (int s = 16; s; s >>= 1) sum += __shfl_xor_sync(0xffffffffu, sum, s);
    __syncthreads();
    if (!lane) red[warp] = sum;
    __syncthreads();
    sum = red[0];
    #pragma unroll
    for (int w = 1; w < 8; w++) sum += red[w];
    const float inv = 1.f / sum;

    for (int i = tid; i < HWD; i += 256) y[i] = __expf(x[i] - m) * inv;
}

// ==================== proxy[n,c,k] = sum_s p[n,k,s] feats[n,c,s] ====================
__global__ __launch_bounds__(256) void proxy_k(const float* __restrict__ feats) {
    const int n = blockIdx.y;
    const int warp = threadIdx.x >> 5, lane = threadIdx.x & 31;
    const int c0 = blockIdx.x * 16 + warp * 2;

    __shared__ __align__(16) float ps[128 * 22];

    u64 acc0[10], acc1[10];
    #pragma unroll
    for (int t = 0; t < 10; t++) { acc0[t] = 0ull; acc1[t] = 0ull; }

    const float* f0p = feats + ((size_t)(n * CIN + c0)) * HWD;
    const float* f1p = f0p + HWD;
    const float* pn  = g_p + (size_t)n * KCL * HWD;

    for (int sc = 0; sc < HWD; sc += 128) {
        __syncthreads();
        for (int idx = threadIdx.x; idx < KCL * 128; idx += 256) {
            int k = idx >> 7, j = idx & 127;
            ps[j * 22 + k] = pn[(size_t)k * HWD + sc + j];
        }
        if (threadIdx.x < 128) ps[threadIdx.x * 22 + 19] = 0.f;
        __syncthreads();

        #pragma unroll
        for (int jj = 0; jj < 4; jj++) {
            int j = lane + jj * 32;
            float f0 = f0p[sc + j];
            float f1 = f1p[sc + j];
            u64 f02 = pk2(f0, f0), f12 = pk2(f1, f1);
            const u64* pr = (const u64*)&ps[j * 22];
            #pragma unroll
            for (int t = 0; t < 10; t++) {
                u64 pv = pr[t];
                ffma2(acc0[t], f02, pv);
                ffma2(acc1[t], f12, pv);
            }
        }
    }
    #pragma unroll
    for (int t = 0; t < 10; t++) {
        #pragma unroll
        for (int s = 16; s; s >>= 1) {
            fadd2(acc0[t], __shfl_xor_sync(0xffffffffu, acc0[t], s));
            fadd2(acc1[t], __shfl_xor_sync(0xffffffffu, acc1[t], s));
        }
    }
    if (lane == 0) {
        float* o0 = g_proxy + (size_t)(n * CIN + c0) * 20;
        float* o1 = o0 + 20;
        #pragma unroll
        for (int t = 0; t < 10; t++) {
            float2 v0 = upk(acc0[t]);
            float2 v1 = upk(acc1[t]);
            o0[2 * t] = v0.x;
            o1[2 * t] = v1.x;
            if (2 * t + 1 < KCL) { o0[2 * t + 1] = v0.y; o1[2 * t + 1] = v1.y; }
        }
    }
}

// ==================== object micro GEMM (with CBR epilogue) ====================
__global__ __launch_bounds__(256) void obj_gemm(
    const float* __restrict__ W, const float* __restrict__ bv,
    const float* __restrict__ sv, const float* __restrict__ tv,
    const float* __restrict__ src, float* __restrict__ dst, int Cin)
{
    extern __shared__ float src_s[];
    const int n = blockIdx.y;
    for (int idx = threadIdx.x; idx < Cin * 20; idx += 256)
        src_s[(idx / 20) * 22 + (idx % 20)] = src[(size_t)n * Cin * 20 + idx];
    __syncthreads();

    const int g  = threadIdx.x & 15;
    const int ol = threadIdx.x >> 4;
    const int o  = blockIdx.x * 16 + ol;

    u64 acc[10];
    #pragma unroll
    for (int t = 0; t < 10; t++) acc[t] = 0ull;

    const float* wrow = W + (size_t)o * Cin;
    const int ncc = Cin >> 4;
    for (int cc = 0; cc < ncc; cc++) {
        int c = g + cc * 16;
        float w = __ldg(&wrow[c]);
        u64 w2 = pk2(w, w);
        const u64* pr = (const u64*)&src_s[c * 22];
        #pragma unroll
        for (int t = 0; t < 10; t++) ffma2(acc[t], w2, pr[t]);
    }
    #pragma unroll
    for (int t = 0; t < 10; t++) {
        #pragma unroll
        for (int s = 8; s; s >>= 1)
            fadd2(acc[t], __shfl_xor_sync(0xffffffffu, acc[t], s));
    }
    if (g == 0) {
        float bi = bv[o], sc = sv[o], ta = tv[o];
        float* dp = dst + (size_t)(n * KC + o) * 20;
        #pragma unroll
        for (int t = 0; t < 10; t++) {
            float2 v = upk(acc[t]);
            dp[2 * t] = fmaxf((v.x + bi) * sc + ta, 0.f);
            if (2 * t + 1 < KCL) dp[2 * t + 1] = fmaxf((v.y + bi) * sc + ta, 0.f);
        }
    }
}

// ==================== Wv[n,o,k] = sum_c wu[o,c] * val[n,c,k]  (raw, no affine) ====================
__global__ __launch_bounds__(256) void wv_gemm(const float* __restrict__ wu) {
    __shared__ float src_s[KC * 22];
    const int n = blockIdx.y;
    for (int idx = threadIdx.x; idx < KC * 20; idx += 256)
        src_s[(idx / 20) * 22 + (idx % 20)] = g_val[(size_t)n * KC * 20 + idx];
    __syncthreads();

    const int g  = threadIdx.x & 15;
    const int ol = threadIdx.x >> 4;
    const int o  = blockIdx.x * 16 + ol;     // grid.x = 32 -> o in 0..511

    u64 acc[10];
    #pragma unroll
    for (int t = 0; t < 10; t++) acc[t] = 0ull;

    const float* wrow = wu + (size_t)o * KC;
    for (int cc = 0; cc < 16; cc++) {
        int c = g + cc * 16;
        float w = __ldg(&wrow[c]);
        u64 w2 = pk2(w, w);
        const u64* pr = (const u64*)&src_s[c * 22];
        #pragma unroll
        for (int t = 0; t < 10; t++) ffma2(acc[t], w2, pr[t]);
    }
    #pragma unroll
    for (int t = 0; t < 10; t++) {
        #pragma unroll
        for (int s = 8; s; s >>= 1)
            fadd2(acc[t], __shfl_xor_sync(0xffffffffu, acc[t], s));
    }
    if (g == 0) {
        float* dp = g_wv + (size_t)(n * OUTC + o) * 20;
        #pragma unroll
        for (int t = 0; t < 10; t++) {
            float2 v = upk(acc[t]);
            dp[2 * t] = v.x;
            if (2 * t + 1 < KCL) dp[2 * t + 1] = v.y;
        }
    }
}

// ==================== converters ====================
__global__ __launch_bounds__(256) void conv_feats2(const float* __restrict__ X) {
    const size_t TOT4 = (size_t)NB * CIN * HWD / 4;
    size_t i4 = (size_t)blockIdx.x * 256 + threadIdx.x;
    if (i4 >= TOT4) return;
    size_t row = i4 >> 12;
    int s = (int)(i4 & 4095) * 4;
    int n = (int)(row >> 9), c = (int)(row & 511);
    float4 v = *(const float4*)(X + row * HWD + s);
    __nv_bfloat16 h0, h1, h2, h3, l0, l1, l2, l3;
    split_bf16(v.x, h0, l0); split_bf16(v.y, h1, l1);
    split_bf16(v.z, h2, l2); split_bf16(v.w, h3, l3);
    __nv_bfloat16* hi = g_feats2 + ((size_t)n * 2 * CIN + c) * HWD + s;
    __nv_bfloat16* lo = hi + (size_t)CIN * HWD;
    *(u32*)hi = pack_bf2(h0, h1); *(u32*)(hi + 2) = pack_bf2(h2, h3);
    *(u32*)lo = pack_bf2(l0, l1); *(u32*)(lo + 2) = pack_bf2(l2, l3);
}

__global__ __launch_bounds__(256) void conv_w(const float* __restrict__ W,
                                              __nv_bfloat16* __restrict__ A2,
                                              int MK) {
    int i = blockIdx.x * 256 + threadIdx.x;
    if (i >= MK) return;
    __nv_bfloat16 h, l;
    split_bf16(W[i], h, l);
    A2[i] = h;
    A2[MK + i] = l;
}

// ==================== cp.async multistage compensated-bf16 GEMM + CBR ====================
#define A_PL 10240                        // 128*40*2 bytes
#define B_PL 8704                         // 32*136*2 bytes
#define ST_BYTES (2 * A_PL + 2 * B_PL)    // 37888
#define GEMM_SMEM (NS * ST_BYTES)         // 113664

__global__ __launch_bounds__(256, 2) void gemm_cp(
    const __nv_bfloat16* __restrict__ W2, int K, int nMB,
    const __nv_bfloat16* __restrict__ B0, long sB0, long pl0,
    const __nv_bfloat16* __restrict__ B1, long sB1, long pl1, int Ksplit,
    const float* __restrict__ bias, const float* __restrict__ scale,
    const float* __restrict__ tadd,
    float* __restrict__ Yf, long sYf,
    __nv_bfloat16* __restrict__ Y2, long sY2, long plY)
{
    extern __shared__ __align__(16) char smem[];
    const u32 sb = smem_u32(smem);

    const int n = blockIdx.z;
    const int m0 = (blockIdx.x % nMB) * BM;
    const int s0 = (blockIdx.x / nMB) * BN;

    const int tid = threadIdx.x;
    const int lane = tid & 31, warp = tid >> 5;
    const int wm = warp >> 2, wn = warp & 3;

    const __nv_bfloat16* b0h = B0 + (size_t)n * sB0;
    const __nv_bfloat16* b0l = b0h + pl0;
    const __nv_bfloat16* b1h = B1 + (size_t)n * sB1;
    const __nv_bfloat16* b1l = b1h + pl1;
    const size_t WloOff = (size_t)nMB * BM * K;

    float acc[4][4][4];
    #pragma unroll
    for (int mi = 0; mi < 4; mi++)
        #pragma unroll
        for (int ni = 0; ni < 4; ni++)
            #pragma unroll
            for (int q = 0; q < 4; q++) acc[mi][ni][q] = 0.f;

    const int nT = K / BK;

    // ---- loader: 8 x 16B cp.async per thread per stage ----
    auto load_stage = [&](int t, int buf) {
        const int kt = t * BK;
        const u32 stBase = sb + buf * ST_BYTES;
        #pragma unroll
        for (int i = 0; i < 8; i++) {
            int id = i * 256 + tid;
            if (id < 1024) {
                int plane = id >> 9, e = id & 511;
                int row = e >> 2, c = e & 3;
                const __nv_bfloat16* src = W2 + (plane ? WloOff : 0)
                    + (size_t)(m0 + row) * K + kt + c * 8;
                cp16(stBase + (plane ? A_PL : 0) + row * 80 + c * 16, src);
            } else {
                int bid = id - 1024;
                int plane = bid >> 9, e = bid & 511;
                int row = e >> 4, c = e & 15;
                int r = kt + row;
                const __nv_bfloat16* base = (r < Ksplit)
                    ? (plane ? b0l : b0h) + (size_t)r * HWD
                    : (plane ? b1l : b1h) + (size_t)(r - Ksplit) * HWD;
                cp16(stBase + 2 * A_PL + (plane ? B_PL : 0) + row * 272 + c * 16,
                     base + s0 + c * 8);
            }
        }
    };

    const u32 aOff = ((wm * 64 + (lane & 15)) * 40 + ((lane >> 4) << 3)) * 2;
    const u32 bOff = ((lane & 15) * 136 + wn * 32 + ((lane >> 4) << 3)) * 2;
    const u32 A_MI = 16 * 40 * 2;
    const u32 B_KS = 16 * 136 * 2;

    // prologue: stages 0, 1
    load_stage(0, 0); CP_COMMIT();
    load_stage(1, 1); CP_COMMIT();

    for (int t = 0; t < nT; t++) {
        CP_WAIT1();
        __syncthreads();
        if (t + 2 < nT) load_stage(t + 2, (t + 2) % NS);
        CP_COMMIT();

        const u32 st = sb + (t % NS) * ST_BYTES;
        const u32 ahA = st + aOff;
        const u32 alA = st + A_PL + aOff;
        const u32 bhA = st + 2 * A_PL + bOff;
        const u32 blA = st + 2 * A_PL + B_PL + bOff;

        #pragma unroll
        for (int ks = 0; ks < 2; ks++) {
            u32 rbh0[4], rbh1[4], rbl0[4], rbl1[4];
            ldsm4t(rbh0, bhA + ks * B_KS);
            ldsm4t(rbh1, bhA + ks * B_KS + 32);
            ldsm4t(rbl0, blA + ks * B_KS);
            ldsm4t(rbl1, blA + ks * B_KS + 32);

            u32 ra[4][4];
            #pragma unroll
            for (int mi = 0; mi < 4; mi++) ldsm4(ra[mi], ahA + mi * A_MI + ks * 32);
            #pragma unroll
            for (int mi = 0; mi < 4; mi++) {
                mma16816(acc[mi][0], ra[mi], &rbh0[0]);
                mma16816(acc[mi][1], ra[mi], &rbh0[2]);
                mma16816(acc[mi][2], ra[mi], &rbh1[0]);
                mma16816(acc[mi][3], ra[mi], &rbh1[2]);
            }
            #pragma unroll
            for (int mi = 0; mi < 4; mi++) {
                mma16816(acc[mi][0], ra[mi], &rbl0[0]);
                mma16816(acc[mi][1], ra[mi], &rbl0[2]);
                mma16816(acc[mi][2], ra[mi], &rbl1[0]);
                mma16816(acc[mi][3], ra[mi], &rbl1[2]);
            }
            #pragma unroll
            for (int mi = 0; mi < 4; mi++) ldsm4(ra[mi], alA + mi * A_MI + ks * 32);
            #pragma unroll
            for (int mi = 0; mi < 4; mi++) {
                mma16816(acc[mi][0], ra[mi], &rbh0[0]);
                mma16816(acc[mi][1], ra[mi], &rbh0[2]);
                mma16816(acc[mi][2], ra[mi], &rbh1[0]);
                mma16816(acc[mi][3], ra[mi], &rbh1[2]);
            }
        }
    }

    // ---- epilogue ----
    const int orow = lane >> 2;
    const int scol = (lane & 3) * 2;
    if (Yf) {
        float* y = Yf + (size_t)n * sYf;
        #pragma unroll
        for (int mi = 0; mi < 4; mi++) {
            const int oA = m0 + wm * 64 + mi * 16 + orow;
            const int oB = oA + 8;
            const float biA = bias[oA], scA = scale[oA], taA = tadd[oA];
            const float biB = bias[oB], scB = scale[oB], taB = tadd[oB];
            #pragma unroll
            for (int ni = 0; ni < 4; ni++) {
                const int s = s0 + wn * 32 + ni * 8 + scol;
                float2 r0 = make_float2(
                    fmaxf((acc[mi][ni][0] + biA) * scA + taA, 0.f),
                    fmaxf((acc[mi][ni][1] + biA) * scA + taA, 0.f));
                float2 r1 = make_float2(
                    fmaxf((acc[mi][ni][2] + biB) * scB + taB, 0.f),
                    fmaxf((acc[mi][ni][3] + biB) * scB + taB, 0.f));
                *(float2*)(y + (size_t)oA * HWD + s) = r0;
                *(float2*)(y + (size_t)oB * HWD + s) = r1;
            }
        }
    } else {
        __nv_bfloat16* yh = Y2 + (size_t)n * sY2;
        __nv_bfloat16* yl = yh + plY;
        #pragma unroll
        for (int mi = 0; mi < 4; mi++) {
            const int oA = m0 + wm * 64 + mi * 16 + orow;
            const int oB = oA + 8;
            const float biA = bias[oA], scA = scale[oA], taA = tadd[oA];
            const float biB = bias[oB], scB = scale[oB], taB = tadd[oB];
            #pragma unroll
            for (int ni = 0; ni < 4; ni++) {
                const int s = s0 + wn * 32 + ni * 8 + scol;
                float vA0 = fmaxf((acc[mi][ni][0] + biA) * scA + taA, 0.f);
                float vA1 = fmaxf((acc[mi][ni][1] + biA) * scA + taA, 0.f);
                float vB0 = fmaxf((acc[mi][ni][2] + biB) * scB + taB, 0.f);
                float vB1 = fmaxf((acc[mi][ni][3] + biB) * scB + taB, 0.f);
                __nv_bfloat16 hA0, lA0, hA1, lA1, hB0, lB0, hB1, lB1;
                split_bf16(vA0, hA0, lA0); split_bf16(vA1, hA1, lA1);
                split_bf16(vB0, hB0, lB0); split_bf16(vB1, hB1, lB1);
                *(u32*)(yh + (size_t)oA * HWD + s) = pack_bf2(hA0, hA1);
                *(u32*)(yl + (size_t)oA * HWD + s) = pack_bf2(lA0, lA1);
                *(u32*)(yh + (size_t)oB * HWD + s) = pack_bf2(hB0, hB1);
                *(u32*)(yl + (size_t)oB * HWD + s) = pack_bf2(lB0, lB1);
            }
        }
    }
}

// ==================== attention + folded f_up ====================
// per position: sim = softmax(q . kk / 16); up[o] = relu((Wv[o].sim + bu)*su + tu)
// block handles 256 positions x 256 output channels (blockIdx.y selects o-half)
__global__ __launch_bounds__(256) void attn_up_k(
    const float* __restrict__ bu, const float* __restrict__ su,
    const float* __restrict__ tu)
{
    const int n = blockIdx.z;
    const int oh = blockIdx.y;             // 0 or 1
    __shared__ __align__(8) float kk_s[KC * 20];
    __shared__ __align__(8) float wv_s[256 * 20];
    __shared__ float prm[3 * 256];

    for (int idx = threadIdx.x; idx < KC * 20; idx += 256)
        kk_s[idx] = g_kk[(size_t)n * KC * 20 + idx];
    for (int idx = threadIdx.x; idx < 256 * 20; idx += 256)
        wv_s[idx] = g_wv[((size_t)n * OUTC + oh * 256) * 20 + idx];
    {
        int o = oh * 256 + threadIdx.x;
        prm[threadIdx.x] = bu[o];
        prm[256 + threadIdx.x] = su[o];
        prm[512 + threadIdx.x] = tu[o];
    }
    __syncthreads();

    const int sa = blockIdx.x * 256 + threadIdx.x;
    const float* qn = g_q2 + (size_t)n * KC * HWD;

    u64 lg[10];
    #pragma unroll
    for (int t = 0; t < 10; t++) lg[t] = 0ull;

    #pragma unroll 4
    for (int c = 0; c < KC; c++) {
        float q = qn[(size_t)c * HWD + sa];
        u64 q2 = pk2(q, q);
        const u64* kr = (const u64*)&kk_s[c * 20];
        #pragma unroll
        for (int t = 0; t < 10; t++) ffma2(lg[t], q2, kr[t]);
    }

    float la[20];
    #pragma unroll
    for (int t = 0; t < 10; t++) {
        float2 v = upk(lg[t]); la[2 * t] = v.x; la[2 * t + 1] = v.y;
    }
    const float scl = 0.0625f;
    float m = -3.4e38f;
    #pragma unroll
    for (int k = 0; k < KCL; k++) { la[k] *= scl; m = fmaxf(m, la[k]); }
    float sum = 0.f;
    #pragma unroll
    for (int k = 0; k < KCL; k++) { la[k] = __expf(la[k] - m); sum += la[k]; }
    const float iv = 1.f / sum;
    #pragma unroll
    for (int k = 0; k < KCL; k++) la[k] *= iv;
    la[19] = 0.f;

    u64 sim2[10];
    #pragma unroll
    for (int t = 0; t < 10; t++) sim2[t] = pk2(la[2 * t], la[2 * t + 1]);

    __nv_bfloat16* uph = g_up2 + ((size_t)n * 2 * CIN + oh * 256) * HWD + sa;
    __nv_bfloat16* upl = uph + (size_t)CIN * HWD;

    #pragma unroll 4
    for (int oo = 0; oo < 256; oo++) {
        const u64* vr = (const u64*)&wv_s[oo * 20];
        u64 a = 0ull;
        #pragma unroll
        for (int t = 0; t < 10; t++) ffma2(a, sim2[t], vr[t]);
        float2 v = upk(a);
        float f = fmaxf(((v.x + v.y) + prm[oo]) * prm[256 + oo] + prm[512 + oo], 0.f);
        __nv_bfloat16 h, l;
        split_bf16(f, h, l);
        uph[(size_t)oo * HWD] = h;
        upl[(size_t)oo * HWD] = l;
    }
}

// ==================== host driver ====================
extern "C" void kernel_launch(void* const* d_in, const int* in_sizes, int n_in,
                              void* d_out, int out_size) {
    const float* feats = (const float*)d_in[0];
    const float* probs = (const float*)d_in[1];
    const float* wp1 = (const float*)d_in[2];
    const float* bp1 = (const float*)d_in[3];
    const float* sp1 = (const float*)d_in[4];
    const float* tp1 = (const float*)d_in[5];
    const float* wp2 = (const float*)d_in[6];
    const float* bp2 = (const float*)d_in[7];
    const float* sp2 = (const float*)d_in[8];
    const float* tp2 = (const float*)d_in[9];
    const float* wo1 = (const float*)d_in[10];
    const float* bo1 = (const float*)d_in[11];
    const float* so1 = (const float*)d_in[12];
    const float* to1 = (const float*)d_in[13];
    const float* wo2 = (const float*)d_in[14];
    const float* bo2 = (const float*)d_in[15];
    const float* so2 = (const float*)d_in[16];
    const float* to2 = (const float*)d_in[17];
    const float* wd  = (const float*)d_in[18];
    const float* bd  = (const float*)d_in[19];
    const float* sd  = (const float*)d_in[20];
    const float* td  = (const float*)d_in[21];
    const float* wu  = (const float*)d_in[22];
    const float* bu  = (const float*)d_in[23];
    const float* su  = (const float*)d_in[24];
    const float* tu  = (const float*)d_in[25];
    const float* wf  = (const float*)d_in[26];
    const float* bf  = (const float*)d_in[27];
    const float* sf  = (const float*)d_in[28];
    const float* tf  = (const float*)d_in[29];
    float* out = (float*)d_out;

    void *pproxy, *pt1, *pkk, *pval, *pq2, *pf2, *pq12, *pup2;
    void *pw1, *pw2, *pwf;
    cudaGetSymbolAddress(&pproxy, g_proxy);
    cudaGetSymbolAddress(&pt1, g_t1);
    cudaGetSymbolAddress(&pkk, g_kk);
    cudaGetSymbolAddress(&pval, g_val);
    cudaGetSymbolAddress(&pq2, g_q2);
    cudaGetSymbolAddress(&pf2, g_feats2);
    cudaGetSymbolAddress(&pq12, g_q12);
    cudaGetSymbolAddress(&pup2, g_up2);
    cudaGetSymbolAddress(&pw1, g_wp1_2);
    cudaGetSymbolAddress(&pw2, g_wp2_2);
    cudaGetSymbolAddress(&pwf, g_wf_2);

    cudaFuncSetAttribute(gemm_cp, cudaFuncAttributeMaxDynamicSharedMemorySize, GEMM_SMEM);

    // converters
    conv_feats2<<<(NB * CIN * HWD / 4 + 255) / 256, 256>>>(feats);
    conv_w<<<(KC * CIN + 255) / 256, 256>>>(wp1, (__nv_bfloat16*)pw1, KC * CIN);
    conv_w<<<(KC * KC + 255) / 256, 256>>>(wp2, (__nv_bfloat16*)pw2, KC * KC);
    conv_w<<<(OUTC * 2 * CIN + 255) / 256, 256>>>(wf, (__nv_bfloat16*)pwf, OUTC * 2 * CIN);

    // softmax + proxy + object branch + Wv
    softmax_k<<<NB * KCL, 256>>>(probs);
    proxy_k<<<dim3(32, NB), 256>>>(feats);
    obj_gemm<<<dim3(16, NB), 256, CIN * 22 * 4>>>(wo1, bo1, so1, to1,
        (const float*)pproxy, (float*)pt1, CIN);
    obj_gemm<<<dim3(16, NB), 256, CIN * 22 * 4>>>(wd, bd, sd, td,
        (const float*)pproxy, (float*)pval, CIN);
    obj_gemm<<<dim3(16, NB), 256, KC * 22 * 4>>>(wo2, bo2, so2, to2,
        (const float*)pt1, (float*)pkk, KC);
    wv_gemm<<<dim3(32, NB), 256>>>(wu);

    // q1 = cbr(wp1 @ feats) -> split planes    M=256, K=512
    gemm_cp<<<dim3((HWD / BN) * (KC / BM), 1, NB), 256, GEMM_SMEM>>>(
        (const __nv_bfloat16*)pw1, CIN, KC / BM,
        (const __nv_bfloat16*)pf2, 2L * CIN * HWD, (long)CIN * HWD,
        (const __nv_bfloat16*)pf2, 2L * CIN * HWD, (long)CIN * HWD, CIN,
        bp1, sp1, tp1,
        nullptr, 0,
        (__nv_bfloat16*)pq12, 2L * KC * HWD, (long)KC * HWD);

    // q2 = cbr(wp2 @ q1) -> fp32               M=256, K=256
    gemm_cp<<<dim3((HWD / BN) * (KC / BM), 1, NB), 256, GEMM_SMEM>>>(
        (const __nv_bfloat16*)pw2, KC, KC / BM,
        (const __nv_bfloat16*)pq12, 2L * KC * HWD, (long)KC * HWD,
        (const __nv_bfloat16*)pq12, 2L * KC * HWD, (long)KC * HWD, KC,
        bp2, sp2, tp2,
        (float*)pq2, (long)KC * HWD,
        nullptr, 0, 0);

    // attention + folded f_up -> up split planes
    attn_up_k<<<dim3(HWD / 256, 2, NB), 256>>>(bu, su, tu);

    // out = cbr(wf @ cat[up, feats]) -> fp32   M=512, K=1024, Ksplit=512
    gemm_cp<<<dim3((HWD / BN) * (OUTC / BM), 1, NB), 256, GEMM_SMEM>>>(
        (const __nv_bfloat16*)pwf, 2 * CIN, OUTC / BM,
        (const __nv_bfloat16*)pup2, 2L * CIN * HWD, (long)CIN * HWD,
        (const __nv_bfloat16*)pf2, 2L * CIN * HWD, (long)CIN * HWD, CIN,
        bf, sf, tf,
        out, (long)OUTC * HWD,
        nullptr, 0, 0);
}

// round 8
// speedup vs baseline: 1.2169x; 1.2169x over previous
#include <cuda_runtime.h>
#include <cuda_bf16.h>
#include <cstdint>

#define NB   4
#define CIN  512
#define HWD  16384
#define KCL  19
#define KC   256
#define OUTC 512

#define BM 128
#define BN 128
#define BK 32

typedef unsigned long long u64;
typedef unsigned int u32;

// ---------------- packed f32x2 helpers ----------------
__device__ __forceinline__ u64 pk2(float lo, float hi) {
    u64 r; asm("mov.b64 %0, {%1, %2};" : "=l"(r) : "f"(lo), "f"(hi)); return r;
}
__device__ __forceinline__ void ffma2(u64& d, u64 a, u64 b) {
    asm("fma.rn.f32x2 %0, %1, %2, %0;" : "+l"(d) : "l"(a), "l"(b));
}
__device__ __forceinline__ void fadd2(u64& d, u64 a) {
    asm("add.rn.f32x2 %0, %0, %1;" : "+l"(d) : "l"(a));
}
__device__ __forceinline__ float2 upk(u64 v) {
    float2 f; asm("mov.b64 {%0, %1}, %2;" : "=f"(f.x), "=f"(f.y) : "l"(v)); return f;
}
__device__ __forceinline__ void split_bf16(float v, __nv_bfloat16& h, __nv_bfloat16& l) {
    h = __float2bfloat16(v);
    l = __float2bfloat16(v - __bfloat162float(h));
}

// ---------------- mma helpers ----------------
__device__ __forceinline__ void ldsm4(u32* r, u32 addr) {
    asm volatile("ldmatrix.sync.aligned.m8n8.x4.shared.b16 {%0,%1,%2,%3}, [%4];\n"
        : "=r"(r[0]), "=r"(r[1]), "=r"(r[2]), "=r"(r[3]) : "r"(addr));
}
__device__ __forceinline__ void ldsm4t(u32* r, u32 addr) {
    asm volatile("ldmatrix.sync.aligned.m8n8.x4.trans.shared.b16 {%0,%1,%2,%3}, [%4];\n"
        : "=r"(r[0]), "=r"(r[1]), "=r"(r[2]), "=r"(r[3]) : "r"(addr));
}
__device__ __forceinline__ void mma16816(float* d, const u32* a, const u32* b) {
    asm volatile(
        "mma.sync.aligned.m16n8k16.row.col.f32.bf16.bf16.f32 "
        "{%0,%1,%2,%3}, {%4,%5,%6,%7}, {%8,%9}, {%0,%1,%2,%3};\n"
        : "+f"(d[0]), "+f"(d[1]), "+f"(d[2]), "+f"(d[3])
        : "r"(a[0]), "r"(a[1]), "r"(a[2]), "r"(a[3]), "r"(b[0]), "r"(b[1]));
}

union U16B {
    __nv_bfloat16 v[16];
    uint4 q[2];
};

// ---------------- scratch (device globals, zero-initialized) ----------------
__device__ float g_p[NB * KCL * HWD];
__device__ float g_proxy[NB * CIN * 20];
__device__ float g_t1[NB * KC * 20];
__device__ float g_kk[NB * KC * 20];
__device__ float g_val[NB * KC * 20];
__device__ float g_wv[NB * OUTC * 20];
__device__ float g_q1[(size_t)NB * KC * HWD];
__device__ float g_q2[(size_t)NB * KC * HWD];
__device__ float g_up[(size_t)NB * CIN * HWD];

// split weights: [hi M*K][lo M*K]
__device__ __nv_bfloat16 g_wp1_2[2 * (size_t)KC * CIN];
__device__ __nv_bfloat16 g_wp2_2[2 * (size_t)KC * KC];
__device__ __nv_bfloat16 g_wf_2[2 * (size_t)OUTC * 2 * CIN];

// ==================== spatial softmax per (n,k) ====================
__global__ __launch_bounds__(256) void softmax_k(const float* __restrict__ probs) {
    const int row = blockIdx.x;
    const float* x = probs + (size_t)row * HWD;
    float* y = g_p + (size_t)row * HWD;
    __shared__ float red[8];
    const int tid = threadIdx.x, lane = tid & 31, warp = tid >> 5;

    float m = -3.4e38f;
    for (int i = tid; i < HWD; i += 256) m = fmaxf(m, x[i]);
    #pragma unroll
    for (int s = 16; s; s >>= 1) m = fmaxf(m, __shfl_xor_sync(0xffffffffu, m, s));
    if (!lane) red[warp] = m;
    __syncthreads();
    m = red[0];
    #pragma unroll
    for (int w = 1; w < 8; w++) m = fmaxf(m, red[w]);

    float sum = 0.f;
    for (int i = tid; i < HWD; i += 256) sum += __expf(x[i] - m);
    #pragma unroll
    for (int s = 16; s; s >>= 1) sum += __shfl_xor_sync(0xffffffffu, sum, s);
    __syncthreads();
    if (!lane) red[warp] = sum;
    __syncthreads();
    sum = red[0];
    #pragma unroll
    for (int w = 1; w < 8; w++) sum += red[w];
    const float inv = 1.f / sum;

    for (int i = tid; i < HWD; i += 256) y[i] = __expf(x[i] - m) * inv;
}

// ==================== proxy[n,c,k] = sum_s p[n,k,s] feats[n,c,s] ====================
__global__ __launch_bounds__(256) void proxy_k(const float* __restrict__ feats) {
    const int n = blockIdx.y;
    const int warp = threadIdx.x >> 5, lane = threadIdx.x & 31;
    const int c0 = blockIdx.x * 16 + warp * 2;

    __shared__ __align__(16) float ps[128 * 22];

    u64 acc0[10], acc1[10];
    #pragma unroll
    for (int t = 0; t < 10; t++) { acc0[t] = 0ull; acc1[t] = 0ull; }

    const float* f0p = feats + ((size_t)(n * CIN + c0)) * HWD;
    const float* f1p = f0p + HWD;
    const float* pn  = g_p + (size_t)n * KCL * HWD;

    for (int sc = 0; sc < HWD; sc += 128) {
        __syncthreads();
        for (int idx = threadIdx.x; idx < KCL * 128; idx += 256) {
            int k = idx >> 7, j = idx & 127;
            ps[j * 22 + k] = pn[(size_t)k * HWD + sc + j];
        }
        if (threadIdx.x < 128) ps[threadIdx.x * 22 + 19] = 0.f;
        __syncthreads();

        #pragma unroll
        for (int jj = 0; jj < 4; jj++) {
            int j = lane + jj * 32;
            float f0 = f0p[sc + j];
            float f1 = f1p[sc + j];
            u64 f02 = pk2(f0, f0), f12 = pk2(f1, f1);
            const u64* pr = (const u64*)&ps[j * 22];
            #pragma unroll
            for (int t = 0; t < 10; t++) {
                u64 pv = pr[t];
                ffma2(acc0[t], f02, pv);
                ffma2(acc1[t], f12, pv);
            }
        }
    }
    #pragma unroll
    for (int t = 0; t < 10; t++) {
        #pragma unroll
        for (int s = 16; s; s >>= 1) {
            fadd2(acc0[t], __shfl_xor_sync(0xffffffffu, acc0[t], s));
            fadd2(acc1[t], __shfl_xor_sync(0xffffffffu, acc1[t], s));
        }
    }
    if (lane == 0) {
        float* o0 = g_proxy + (size_t)(n * CIN + c0) * 20;
        float* o1 = o0 + 20;
        #pragma unroll
        for (int t = 0; t < 10; t++) {
            float2 v0 = upk(acc0[t]);
            float2 v1 = upk(acc1[t]);
            o0[2 * t] = v0.x;
            o1[2 * t] = v1.x;
            if (2 * t + 1 < KCL) { o0[2 * t + 1] = v0.y; o1[2 * t + 1] = v1.y; }
        }
    }
}

// ==================== object micro GEMM (CBR epilogue) ====================
__global__ __launch_bounds__(256) void obj_gemm(
    const float* __restrict__ W, const float* __restrict__ bv,
    const float* __restrict__ sv, const float* __restrict__ tv,
    const float* __restrict__ src, float* __restrict__ dst, int Cin)
{
    extern __shared__ float src_s[];
    const int n = blockIdx.y;
    for (int idx = threadIdx.x; idx < Cin * 20; idx += 256)
        src_s[(idx / 20) * 22 + (idx % 20)] = src[(size_t)n * Cin * 20 + idx];
    __syncthreads();

    const int g  = threadIdx.x & 15;
    const int ol = threadIdx.x >> 4;
    const int o  = blockIdx.x * 16 + ol;

    u64 acc[10];
    #pragma unroll
    for (int t = 0; t < 10; t++) acc[t] = 0ull;

    const float* wrow = W + (size_t)o * Cin;
    const int ncc = Cin >> 4;
    for (int cc = 0; cc < ncc; cc++) {
        int c = g + cc * 16;
        float w = __ldg(&wrow[c]);
        u64 w2 = pk2(w, w);
        const u64* pr = (const u64*)&src_s[c * 22];
        #pragma unroll
        for (int t = 0; t < 10; t++) ffma2(acc[t], w2, pr[t]);
    }
    #pragma unroll
    for (int t = 0; t < 10; t++) {
        #pragma unroll
        for (int s = 8; s; s >>= 1)
            fadd2(acc[t], __shfl_xor_sync(0xffffffffu, acc[t], s));
    }
    if (g == 0) {
        float bi = bv[o], sc = sv[o], ta = tv[o];
        float* dp = dst + (size_t)(n * KC + o) * 20;
        #pragma unroll
        for (int t = 0; t < 10; t++) {
            float2 v = upk(acc[t]);
            dp[2 * t] = fmaxf((v.x + bi) * sc + ta, 0.f);
            if (2 * t + 1 < KCL) dp[2 * t + 1] = fmaxf((v.y + bi) * sc + ta, 0.f);
        }
    }
}

// ==================== Wv[n,o,k] = sum_c wu[o,c] * val[n,c,k] (raw) ====================
__global__ __launch_bounds__(256) void wv_gemm(const float* __restrict__ wu) {
    __shared__ float src_s[KC * 22];
    const int n = blockIdx.y;
    for (int idx = threadIdx.x; idx < KC * 20; idx += 256)
        src_s[(idx / 20) * 22 + (idx % 20)] = g_val[(size_t)n * KC * 20 + idx];
    __syncthreads();

    const int g  = threadIdx.x & 15;
    const int ol = threadIdx.x >> 4;
    const int o  = blockIdx.x * 16 + ol;     // grid.x = 32

    u64 acc[10];
    #pragma unroll
    for (int t = 0; t < 10; t++) acc[t] = 0ull;

    const float* wrow = wu + (size_t)o * KC;
    for (int cc = 0; cc < 16; cc++) {
        int c = g + cc * 16;
        float w = __ldg(&wrow[c]);
        u64 w2 = pk2(w, w);
        const u64* pr = (const u64*)&src_s[c * 22];
        #pragma unroll
        for (int t = 0; t < 10; t++) ffma2(acc[t], w2, pr[t]);
    }
    #pragma unroll
    for (int t = 0; t < 10; t++) {
        #pragma unroll
        for (int s = 8; s; s >>= 1)
            fadd2(acc[t], __shfl_xor_sync(0xffffffffu, acc[t], s));
    }
    if (g == 0) {
        float* dp = g_wv + (size_t)(n * OUTC + o) * 20;
        #pragma unroll
        for (int t = 0; t < 10; t++) {
            float2 v = upk(acc[t]);
            dp[2 * t] = v.x;
            if (2 * t + 1 < KCL) dp[2 * t + 1] = v.y;
        }
    }
}

// ==================== weight splitter ====================
__global__ __launch_bounds__(256) void conv_w(const float* __restrict__ W,
                                              __nv_bfloat16* __restrict__ A2,
                                              int MK) {
    int i = blockIdx.x * 256 + threadIdx.x;
    if (i >= MK) return;
    __nv_bfloat16 h, l;
    split_bf16(W[i], h, l);
    A2[i] = h;
    A2[MK + i] = l;
}

// ==================== compensated-bf16 MMA GEMM + fused CBR (R4-proven) ====================
__global__ __launch_bounds__(256, 2) void gemm_mma_cbr(
    const __nv_bfloat16* __restrict__ A2, int K, int nMB,
    const float* __restrict__ B0, const float* __restrict__ B1, int Ksplit,
    const float* __restrict__ bias, const float* __restrict__ scale,
    const float* __restrict__ tadd,
    float* __restrict__ Y, long sB0, long sB1, long sY)
{
    const int n = blockIdx.z;
    const int mIdx = blockIdx.x % nMB;
    const int sIdx = blockIdx.x / nMB;
    const int m0 = mIdx * BM;
    const int s0 = sIdx * BN;

    const int tid = threadIdx.x;
    const int lane = tid & 31, warp = tid >> 5;
    const int wm = warp >> 2, wn = warp & 3;

    extern __shared__ __align__(16) char smem[];
    __nv_bfloat16* AsH = (__nv_bfloat16*)smem;
    __nv_bfloat16* AsL = AsH + 2 * BM * (BK + 8);
    __nv_bfloat16* BsH = AsL + 2 * BM * (BK + 8);
    __nv_bfloat16* BsL = BsH + 2 * BK * (BN + 8);

    const float* b0 = B0 + (size_t)n * sB0;
    const float* b1 = B1 + (size_t)n * sB1;

    const int aRow  = tid >> 1;
    const int aCol  = (tid & 1) * 16;
    const int bRow  = tid >> 3;
    const int bColF = (tid & 7) * 16;

    const __nv_bfloat16* aGh = A2 + (size_t)(m0 + aRow) * K + aCol;
    const __nv_bfloat16* aGl = aGh + (size_t)BM * nMB * K;
    const int sOff = s0 + bColF;

    float acc[4][4][4];
    #pragma unroll
    for (int mi = 0; mi < 4; mi++)
        #pragma unroll
        for (int ni = 0; ni < 4; ni++)
            #pragma unroll
            for (int q = 0; q < 4; q++) acc[mi][ni][q] = 0.f;

    u32 ahBase = (u32)__cvta_generic_to_shared(AsH);
    u32 alBase = (u32)__cvta_generic_to_shared(AsL);
    u32 bhBase = (u32)__cvta_generic_to_shared(BsH);
    u32 blBase = (u32)__cvta_generic_to_shared(BsL);
    const u32 aBuf = BM * (BK + 8) * 2;
    const u32 bBuf = BK * (BN + 8) * 2;
    const u32 aOff = ((wm * 64 + (lane & 15)) * (BK + 8) + ((lane >> 4) << 3)) * 2;
    const u32 bOff = ((lane & 15) * (BN + 8) + wn * 32 + ((lane >> 4) << 3)) * 2;
    const u32 A_MI = 16 * (BK + 8) * 2;
    const u32 B_KS = 16 * (BN + 8) * 2;

    const int nT = K / BK;
    uint4 pah0, pah1, pal0, pal1;
    float4 pb[4];

    {
        pah0 = *(const uint4*)aGh;
        pah1 = *(const uint4*)(aGh + 8);
        pal0 = *(const uint4*)aGl;
        pal1 = *(const uint4*)(aGl + 8);
        int r = bRow;
        const float* rp = (r < Ksplit) ? b0 + (size_t)r * HWD
                                       : b1 + (size_t)(r - Ksplit) * HWD;
        rp += sOff;
        pb[0] = *(const float4*)rp;
        pb[1] = *(const float4*)(rp + 4);
        pb[2] = *(const float4*)(rp + 8);
        pb[3] = *(const float4*)(rp + 12);
    }

    for (int t = 0; t < nT; t++) {
        const int buf = t & 1;
        *(uint4*)&AsH[buf * BM * (BK + 8) + aRow * (BK + 8) + aCol]     = pah0;
        *(uint4*)&AsH[buf * BM * (BK + 8) + aRow * (BK + 8) + aCol + 8] = pah1;
        *(uint4*)&AsL[buf * BM * (BK + 8) + aRow * (BK + 8) + aCol]     = pal0;
        *(uint4*)&AsL[buf * BM * (BK + 8) + aRow * (BK + 8) + aCol + 8] = pal1;
        {
            U16B hh, ll;
            const float* pf = (const float*)pb;
            #pragma unroll
            for (int j = 0; j < 16; j++) {
                __nv_bfloat16 h, l;
                split_bf16(pf[j], h, l);
                hh.v[j] = h; ll.v[j] = l;
            }
            __nv_bfloat16* dh = &BsH[buf * BK * (BN + 8) + bRow * (BN + 8) + bColF];
            __nv_bfloat16* dl = &BsL[buf * BK * (BN + 8) + bRow * (BN + 8) + bColF];
            *(uint4*)dh = hh.q[0];
            *(uint4*)(dh + 8) = hh.q[1];
            *(uint4*)dl = ll.q[0];
            *(uint4*)(dl + 8) = ll.q[1];
        }
        __syncthreads();

        if (t + 1 < nT) {
            const __nv_bfloat16* agh = aGh + (size_t)(t + 1) * BK;
            const __nv_bfloat16* agl = aGl + (size_t)(t + 1) * BK;
            pah0 = *(const uint4*)agh;
            pah1 = *(const uint4*)(agh + 8);
            pal0 = *(const uint4*)agl;
            pal1 = *(const uint4*)(agl + 8);
            int r = (t + 1) * BK + bRow;
            const float* rp = (r < Ksplit) ? b0 + (size_t)r * HWD
                                           : b1 + (size_t)(r - Ksplit) * HWD;
            rp += sOff;
            pb[0] = *(const float4*)rp;
            pb[1] = *(const float4*)(rp + 4);
            pb[2] = *(const float4*)(rp + 8);
            pb[3] = *(const float4*)(rp + 12);
        }

        const u32 ahA = ahBase + aOff + buf * aBuf;
        const u32 alA = alBase + aOff + buf * aBuf;
        const u32 bhA = bhBase + bOff + buf * bBuf;
        const u32 blA = blBase + bOff + buf * bBuf;

        #pragma unroll
        for (int ks = 0; ks < 2; ks++) {
            u32 rbh0[4], rbh1[4], rbl0[4], rbl1[4];
            ldsm4t(rbh0, bhA + ks * B_KS);
            ldsm4t(rbh1, bhA + ks * B_KS + 32);
            ldsm4t(rbl0, blA + ks * B_KS);
            ldsm4t(rbl1, blA + ks * B_KS + 32);

            u32 ra[4][4];
            #pragma unroll
            for (int mi = 0; mi < 4; mi++) ldsm4(ra[mi], ahA + mi * A_MI + ks * 32);
            #pragma unroll
            for (int mi = 0; mi < 4; mi++) {
                mma16816(acc[mi][0], ra[mi], &rbh0[0]);
                mma16816(acc[mi][1], ra[mi], &rbh0[2]);
                mma16816(acc[mi][2], ra[mi], &rbh1[0]);
                mma16816(acc[mi][3], ra[mi], &rbh1[2]);
            }
            #pragma unroll
            for (int mi = 0; mi < 4; mi++) {
                mma16816(acc[mi][0], ra[mi], &rbl0[0]);
                mma16816(acc[mi][1], ra[mi], &rbl0[2]);
                mma16816(acc[mi][2], ra[mi], &rbl1[0]);
                mma16816(acc[mi][3], ra[mi], &rbl1[2]);
            }
            #pragma unroll
            for (int mi = 0; mi < 4; mi++) ldsm4(ra[mi], alA + mi * A_MI + ks * 32);
            #pragma unroll
            for (int mi = 0; mi < 4; mi++) {
                mma16816(acc[mi][0], ra[mi], &rbh0[0]);
                mma16816(acc[mi][1], ra[mi], &rbh0[2]);
                mma16816(acc[mi][2], ra[mi], &rbh1[0]);
                mma16816(acc[mi][3], ra[mi], &rbh1[2]);
            }
        }
        __syncthreads();
    }

    const int orow = lane >> 2;
    const int scol = (lane & 3) * 2;
    float* y = Y + (size_t)n * sY;
    #pragma unroll
    for (int mi = 0; mi < 4; mi++) {
        const int oA = m0 + wm * 64 + mi * 16 + orow;
        const int oB = oA + 8;
        const float biA = bias[oA], scA = scale[oA], taA = tadd[oA];
        const float biB = bias[oB], scB = scale[oB], taB = tadd[oB];
        #pragma unroll
        for (int ni = 0; ni < 4; ni++) {
            const int s = s0 + wn * 32 + ni * 8 + scol;
            float2 r0 = make_float2(
                fmaxf((acc[mi][ni][0] + biA) * scA + taA, 0.f),
                fmaxf((acc[mi][ni][1] + biA) * scA + taA, 0.f));
            float2 r1 = make_float2(
                fmaxf((acc[mi][ni][2] + biB) * scB + taB, 0.f),
                fmaxf((acc[mi][ni][3] + biB) * scB + taB, 0.f));
            *(float2*)(y + (size_t)oA * HWD + s) = r0;
            *(float2*)(y + (size_t)oB * HWD + s) = r1;
        }
    }
}

// ==================== attention + folded f_up (writes up fp32) ====================
__global__ __launch_bounds__(256) void attn_up_k(
    const float* __restrict__ bu, const float* __restrict__ su,
    const float* __restrict__ tu)
{
    const int n = blockIdx.z;
    const int oh = blockIdx.y;             // 0 or 1
    __shared__ __align__(8) float kk_s[KC * 20];
    __shared__ __align__(8) float wv_s[256 * 20];
    __shared__ float prm[3 * 256];

    for (int idx = threadIdx.x; idx < KC * 20; idx += 256)
        kk_s[idx] = g_kk[(size_t)n * KC * 20 + idx];
    for (int idx = threadIdx.x; idx < 256 * 20; idx += 256)
        wv_s[idx] = g_wv[((size_t)n * OUTC + oh * 256) * 20 + idx];
    {
        int o = oh * 256 + threadIdx.x;
        prm[threadIdx.x] = bu[o];
        prm[256 + threadIdx.x] = su[o];
        prm[512 + threadIdx.x] = tu[o];
    }
    __syncthreads();

    const int sa = blockIdx.x * 256 + threadIdx.x;
    const float* qn = g_q2 + (size_t)n * KC * HWD;

    u64 lg[10];
    #pragma unroll
    for (int t = 0; t < 10; t++) lg[t] = 0ull;

    #pragma unroll 4
    for (int c = 0; c < KC; c++) {
        float q = qn[(size_t)c * HWD + sa];
        u64 q2 = pk2(q, q);
        const u64* kr = (const u64*)&kk_s[c * 20];
        #pragma unroll
        for (int t = 0; t < 10; t++) ffma2(lg[t], q2, kr[t]);
    }

    float la[20];
    #pragma unroll
    for (int t = 0; t < 10; t++) {
        float2 v = upk(lg[t]); la[2 * t] = v.x; la[2 * t + 1] = v.y;
    }
    const float scl = 0.0625f;
    float m = -3.4e38f;
    #pragma unroll
    for (int k = 0; k < KCL; k++) { la[k] *= scl; m = fmaxf(m, la[k]); }
    float sum = 0.f;
    #pragma unroll
    for (int k = 0; k < KCL; k++) { la[k] = __expf(la[k] - m); sum += la[k]; }
    const float iv = 1.f / sum;
    #pragma unroll
    for (int k = 0; k < KCL; k++) la[k] *= iv;
    la[19] = 0.f;

    u64 sim2[10];
    #pragma unroll
    for (int t = 0; t < 10; t++) sim2[t] = pk2(la[2 * t], la[2 * t + 1]);

    float* up = g_up + ((size_t)n * CIN + oh * 256) * HWD + sa;

    #pragma unroll 4
    for (int oo = 0; oo < 256; oo++) {
        const u64* vr = (const u64*)&wv_s[oo * 20];
        u64 a = 0ull;
        #pragma unroll
        for (int t = 0; t < 10; t++) ffma2(a, sim2[t], vr[t]);
        float2 v = upk(a);
        up[(size_t)oo * HWD] =
            fmaxf(((v.x + v.y) + prm[oo]) * prm[256 + oo] + prm[512 + oo], 0.f);
    }
}

// ==================== host driver ====================
extern "C" void kernel_launch(void* const* d_in, const int* in_sizes, int n_in,
                              void* d_out, int out_size) {
    const float* feats = (const float*)d_in[0];
    const float* probs = (const float*)d_in[1];
    const float* wp1 = (const float*)d_in[2];
    const float* bp1 = (const float*)d_in[3];
    const float* sp1 = (const float*)d_in[4];
    const float* tp1 = (const float*)d_in[5];
    const float* wp2 = (const float*)d_in[6];
    const float* bp2 = (const float*)d_in[7];
    const float* sp2 = (const float*)d_in[8];
    const float* tp2 = (const float*)d_in[9];
    const float* wo1 = (const float*)d_in[10];
    const float* bo1 = (const float*)d_in[11];
    const float* so1 = (const float*)d_in[12];
    const float* to1 = (const float*)d_in[13];
    const float* wo2 = (const float*)d_in[14];
    const float* bo2 = (const float*)d_in[15];
    const float* so2 = (const float*)d_in[16];
    const float* to2 = (const float*)d_in[17];
    const float* wd  = (const float*)d_in[18];
    const float* bd  = (const float*)d_in[19];
    const float* sd  = (const float*)d_in[20];
    const float* td  = (const float*)d_in[21];
    const float* wu  = (const float*)d_in[22];
    const float* bu  = (const float*)d_in[23];
    const float* su  = (const float*)d_in[24];
    const float* tu  = (const float*)d_in[25];
    const float* wf  = (const float*)d_in[26];
    const float* bf  = (const float*)d_in[27];
    const float* sf  = (const float*)d_in[28];
    const float* tf  = (const float*)d_in[29];
    float* out = (float*)d_out;

    void *pproxy, *pt1, *pkk, *pval, *pq1, *pq2, *pup;
    void *pw1, *pw2, *pwf;
    cudaGetSymbolAddress(&pproxy, g_proxy);
    cudaGetSymbolAddress(&pt1, g_t1);
    cudaGetSymbolAddress(&pkk, g_kk);
    cudaGetSymbolAddress(&pval, g_val);
    cudaGetSymbolAddress(&pq1, g_q1);
    cudaGetSymbolAddress(&pq2, g_q2);
    cudaGetSymbolAddress(&pup, g_up);
    cudaGetSymbolAddress(&pw1, g_wp1_2);
    cudaGetSymbolAddress(&pw2, g_wp2_2);
    cudaGetSymbolAddress(&pwf, g_wf_2);

    const int SMEM_GEMM = (2 * BM * (BK + 8) * 2 + 2 * BK * (BN + 8) * 2) * 2; // 75776 B
    cudaFuncSetAttribute(gemm_mma_cbr, cudaFuncAttributeMaxDynamicSharedMemorySize, SMEM_GEMM);

    // weight splits
    conv_w<<<(KC * CIN + 255) / 256, 256>>>(wp1, (__nv_bfloat16*)pw1, KC * CIN);
    conv_w<<<(KC * KC + 255) / 256, 256>>>(wp2, (__nv_bfloat16*)pw2, KC * KC);
    conv_w<<<(OUTC * 2 * CIN + 255) / 256, 256>>>(wf, (__nv_bfloat16*)pwf, OUTC * 2 * CIN);

    // softmax + proxy + object branch + Wv
    softmax_k<<<NB * KCL, 256>>>(probs);
    proxy_k<<<dim3(32, NB), 256>>>(feats);
    obj_gemm<<<dim3(16, NB), 256, CIN * 22 * 4>>>(wo1, bo1, so1, to1,
        (const float*)pproxy, (float*)pt1, CIN);
    obj_gemm<<<dim3(16, NB), 256, CIN * 22 * 4>>>(wd, bd, sd, td,
        (const float*)pproxy, (float*)pval, CIN);
    obj_gemm<<<dim3(16, NB), 256, KC * 22 * 4>>>(wo2, bo2, so2, to2,
        (const float*)pt1, (float*)pkk, KC);
    wv_gemm<<<dim3(32, NB), 256>>>(wu);

    // f_pixel stage 1: q1 = cbr(wp1 @ feats)     M=256, K=512
    gemm_mma_cbr<<<dim3((HWD / BN) * (KC / BM), 1, NB), 256, SMEM_GEMM>>>(
        (const __nv_bfloat16*)pw1, CIN, KC / BM,
        feats, feats, CIN, bp1, sp1, tp1,
        (float*)pq1, (long)CIN * HWD, (long)CIN * HWD, (long)KC * HWD);

    // f_pixel stage 2: q2 = cbr(wp2 @ q1)        M=256, K=256
    gemm_mma_cbr<<<dim3((HWD / BN) * (KC / BM), 1, NB), 256, SMEM_GEMM>>>(
        (const __nv_bfloat16*)pw2, KC, KC / BM,
        (const float*)pq1, (const float*)pq1, KC, bp2, sp2, tp2,
        (float*)pq2, (long)KC * HWD, (long)KC * HWD, (long)KC * HWD);

    // attention + folded f_up -> up (fp32)
    attn_up_k<<<dim3(HWD / 256, 2, NB), 256>>>(bu, su, tu);

    // final: out = cbr(wf @ cat[up, feats])      M=512, K=1024, Ksplit=512
    gemm_mma_cbr<<<dim3((HWD / BN) * (OUTC / BM), 1, NB), 256, SMEM_GEMM>>>(
        (const __nv_bfloat16*)pwf, 2 * CIN, OUTC / BM,
        (const float*)pup, feats, CIN, bf, sf, tf,
        out, (long)OUTC * HWD, (long)CIN * HWD, (long)OUTC * HWD);
}

// round 10
// speedup vs baseline: 1.4705x; 1.2084x over previous
#include <cuda_runtime.h>
#include <cuda_bf16.h>
#include <cstdint>

#define NB   4
#define CIN  512
#define HWD  16384
#define KCL  19
#define KC   256
#define OUTC 512

#define BM 128
#define BN 128
#define BK 32

typedef unsigned long long u64;
typedef unsigned int u32;

// ---------------- packed f32x2 helpers ----------------
__device__ __forceinline__ u64 pk2(float lo, float hi) {
    u64 r; asm("mov.b64 %0, {%1, %2};" : "=l"(r) : "f"(lo), "f"(hi)); return r;
}
__device__ __forceinline__ void ffma2(u64& d, u64 a, u64 b) {
    asm("fma.rn.f32x2 %0, %1, %2, %0;" : "+l"(d) : "l"(a), "l"(b));
}
__device__ __forceinline__ void fadd2(u64& d, u64 a) {
    asm("add.rn.f32x2 %0, %0, %1;" : "+l"(d) : "l"(a));
}
__device__ __forceinline__ float2 upk(u64 v) {
    float2 f; asm("mov.b64 {%0, %1}, %2;" : "=f"(f.x), "=f"(f.y) : "l"(v)); return f;
}
__device__ __forceinline__ void split_bf16(float v, __nv_bfloat16& h, __nv_bfloat16& l) {
    h = __float2bfloat16(v);
    l = __float2bfloat16(v - __bfloat162float(h));
}
__device__ __forceinline__ u32 pack_bf2(__nv_bfloat16 a, __nv_bfloat16 b) {
    __nv_bfloat162 t; t.x = a; t.y = b;
    return *reinterpret_cast<u32*>(&t);
}

// ---------------- mma / async helpers ----------------
__device__ __forceinline__ u32 smem_u32(const void* p) {
    u32 a;
    asm("{ .reg .u64 t; cvta.to.shared.u64 t, %1; cvt.u32.u64 %0, t; }" : "=r"(a) : "l"(p));
    return a;
}
__device__ __forceinline__ void ldsm4(u32* r, u32 addr) {
    asm volatile("ldmatrix.sync.aligned.m8n8.x4.shared.b16 {%0,%1,%2,%3}, [%4];\n"
        : "=r"(r[0]), "=r"(r[1]), "=r"(r[2]), "=r"(r[3]) : "r"(addr));
}
__device__ __forceinline__ void ldsm4t(u32* r, u32 addr) {
    asm volatile("ldmatrix.sync.aligned.m8n8.x4.trans.shared.b16 {%0,%1,%2,%3}, [%4];\n"
        : "=r"(r[0]), "=r"(r[1]), "=r"(r[2]), "=r"(r[3]) : "r"(addr));
}
__device__ __forceinline__ void mma16816(float* d, const u32* a, const u32* b) {
    asm volatile(
        "mma.sync.aligned.m16n8k16.row.col.f32.bf16.bf16.f32 "
        "{%0,%1,%2,%3}, {%4,%5,%6,%7}, {%8,%9}, {%0,%1,%2,%3};\n"
        : "+f"(d[0]), "+f"(d[1]), "+f"(d[2]), "+f"(d[3])
        : "r"(a[0]), "r"(a[1]), "r"(a[2]), "r"(a[3]), "r"(b[0]), "r"(b[1]));
}
__device__ __forceinline__ void cp16(u32 dst, const void* src) {
    asm volatile("cp.async.cg.shared.global [%0], [%1], 16;" :: "r"(dst), "l"(src) : "memory");
}
#define CP_COMMIT() asm volatile("cp.async.commit_group;" ::: "memory")
#define CP_WAIT0()  asm volatile("cp.async.wait_group 0;" ::: "memory")

// ---------------- scratch (device globals, zero-initialized) ----------------
__device__ float g_p[NB * KCL * HWD];
__device__ float g_proxy[NB * CIN * 20];
__device__ float g_t1[NB * KC * 20];
__device__ float g_kk[NB * KC * 20];
__device__ float g_val[NB * KC * 20];
__device__ float g_wv[NB * OUTC * 20];
__device__ float g_q2[(size_t)NB * KC * HWD];

// split bf16 activation planes: [n][hi plane | lo plane]
__device__ __nv_bfloat16 g_feats2[(size_t)NB * 2 * CIN * HWD];
__device__ __nv_bfloat16 g_q12[(size_t)NB * 2 * KC * HWD];
__device__ __nv_bfloat16 g_up2[(size_t)NB * 2 * CIN * HWD];

// split weights: [hi M*K][lo M*K]
__device__ __nv_bfloat16 g_wp1_2[2 * (size_t)KC * CIN];
__device__ __nv_bfloat16 g_wp2_2[2 * (size_t)KC * KC];
__device__ __nv_bfloat16 g_wf_2[2 * (size_t)OUTC * 2 * CIN];

// ==================== spatial softmax per (n,k) ====================
__global__ __launch_bounds__(256) void softmax_k(const float* __restrict__ probs) {
    const int row = blockIdx.x;
    const float* x = probs + (size_t)row * HWD;
    float* y = g_p + (size_t)row * HWD;
    __shared__ float red[8];
    const int tid = threadIdx.x, lane = tid & 31, warp = tid >> 5;

    float m = -3.4e38f;
    for (int i = tid; i < HWD; i += 256) m = fmaxf(m, x[i]);
    #pragma unroll
    for (int s = 16; s; s >>= 1) m = fmaxf(m, __shfl_xor_sync(0xffffffffu, m, s));
    if (!lane) red[warp] = m;
    __syncthreads();
    m = red[0];
    #pragma unroll
    for (int w = 1; w < 8; w++) m = fmaxf(m, red[w]);

    float sum = 0.f;
    for (int i = tid; i < HWD; i += 256) sum += __expf(x[i] - m);
    #pragma unroll
    for (int s = 16; s; s >>= 1) sum += __shfl_xor_sync(0xffffffffu, sum, s);
    __syncthreads();
    if (!lane) red[warp] = sum;
    __syncthreads();
    sum = red[0];
    #pragma unroll
    for (int w = 1; w < 8; w++) sum += red[w];
    const float inv = 1.f / sum;

    for (int i = tid; i < HWD; i += 256) y[i] = __expf(x[i] - m) * inv;
}

// ==================== proxy[n,c,k] = sum_s p[n,k,s] feats[n,c,s] ====================
__global__ __launch_bounds__(256) void proxy_k(const float* __restrict__ feats) {
    const int n = blockIdx.y;
    const int warp = threadIdx.x >> 5, lane = threadIdx.x & 31;
    const int c0 = blockIdx.x * 16 + warp * 2;

    __shared__ __align__(16) float ps[128 * 22];

    u64 acc0[10], acc1[10];
    #pragma unroll
    for (int t = 0; t < 10; t++) { acc0[t] = 0ull; acc1[t] = 0ull; }

    const float* f0p = feats + ((size_t)(n * CIN + c0)) * HWD;
    const float* f1p = f0p + HWD;
    const float* pn  = g_p + (size_t)n * KCL * HWD;

    for (int sc = 0; sc < HWD; sc += 128) {
        __syncthreads();
        for (int idx = threadIdx.x; idx < KCL * 128; idx += 256) {
            int k = idx >> 7, j = idx & 127;
            ps[j * 22 + k] = pn[(size_t)k * HWD + sc + j];
        }
        if (threadIdx.x < 128) ps[threadIdx.x * 22 + 19] = 0.f;
        __syncthreads();

        #pragma unroll
        for (int jj = 0; jj < 4; jj++) {
            int j = lane + jj * 32;
            float f0 = f0p[sc + j];
            float f1 = f1p[sc + j];
            u64 f02 = pk2(f0, f0), f12 = pk2(f1, f1);
            const u64* pr = (const u64*)&ps[j * 22];
            #pragma unroll
            for (int t = 0; t < 10; t++) {
                u64 pv = pr[t];
                ffma2(acc0[t], f02, pv);
                ffma2(acc1[t], f12, pv);
            }
        }
    }
    #pragma unroll
    for (int t = 0; t < 10; t++) {
        #pragma unroll
        for (int s = 16; s; s >>= 1) {
            fadd2(acc0[t], __shfl_xor_sync(0xffffffffu, acc0[t], s));
            fadd2(acc1[t], __shfl_xor_sync(0xffffffffu, acc1[t], s));
        }
    }
    if (lane == 0) {
        float* o0 = g_proxy + (size_t)(n * CIN + c0) * 20;
        float* o1 = o0 + 20;
        #pragma unroll
        for (int t = 0; t < 10; t++) {
            float2 v0 = upk(acc0[t]);
            float2 v1 = upk(acc1[t]);
            o0[2 * t] = v0.x;
            o1[2 * t] = v1.x;
            if (2 * t + 1 < KCL) { o0[2 * t + 1] = v0.y; o1[2 * t + 1] = v1.y; }
        }
    }
}

// ==================== object micro GEMM (CBR epilogue) ====================
__global__ __launch_bounds__(256) void obj_gemm(
    const float* __restrict__ W, const float* __restrict__ bv,
    const float* __restrict__ sv, const float* __restrict__ tv,
    const float* __restrict__ src, float* __restrict__ dst, int Cin)
{
    extern __shared__ float src_s[];
    const int n = blockIdx.y;
    for (int idx = threadIdx.x; idx < Cin * 20; idx += 256)
        src_s[(idx / 20) * 22 + (idx % 20)] = src[(size_t)n * Cin * 20 + idx];
    __syncthreads();

    const int g  = threadIdx.x & 15;
    const int ol = threadIdx.x >> 4;
    const int o  = blockIdx.x * 16 + ol;

    u64 acc[10];
    #pragma unroll
    for (int t = 0; t < 10; t++) acc[t] = 0ull;

    const float* wrow = W + (size_t)o * Cin;
    const int ncc = Cin >> 4;
    for (int cc = 0; cc < ncc; cc++) {
        int c = g + cc * 16;
        float w = __ldg(&wrow[c]);
        u64 w2 = pk2(w, w);
        const u64* pr = (const u64*)&src_s[c * 22];
        #pragma unroll
        for (int t = 0; t < 10; t++) ffma2(acc[t], w2, pr[t]);
    }
    #pragma unroll
    for (int t = 0; t < 10; t++) {
        #pragma unroll
        for (int s = 8; s; s >>= 1)
            fadd2(acc[t], __shfl_xor_sync(0xffffffffu, acc[t], s));
    }
    if (g == 0) {
        float bi = bv[o], sc = sv[o], ta = tv[o];
        float* dp = dst + (size_t)(n * KC + o) * 20;
        #pragma unroll
        for (int t = 0; t < 10; t++) {
            float2 v = upk(acc[t]);
            dp[2 * t] = fmaxf((v.x + bi) * sc + ta, 0.f);
            if (2 * t + 1 < KCL) dp[2 * t + 1] = fmaxf((v.y + bi) * sc + ta, 0.f);
        }
    }
}

// ==================== Wv[n,o,k] = sum_c wu[o,c] * val[n,c,k] (raw) ====================
__global__ __launch_bounds__(256) void wv_gemm(const float* __restrict__ wu) {
    __shared__ float src_s[KC * 22];
    const int n = blockIdx.y;
    for (int idx = threadIdx.x; idx < KC * 20; idx += 256)
        src_s[(idx / 20) * 22 + (idx % 20)] = g_val[(size_t)n * KC * 20 + idx];
    __syncthreads();

    const int g  = threadIdx.x & 15;
    const int ol = threadIdx.x >> 4;
    const int o  = blockIdx.x * 16 + ol;     // grid.x = 32

    u64 acc[10];
    #pragma unroll
    for (int t = 0; t < 10; t++) acc[t] = 0ull;

    const float* wrow = wu + (size_t)o * KC;
    for (int cc = 0; cc < 16; cc++) {
        int c = g + cc * 16;
        float w = __ldg(&wrow[c]);
        u64 w2 = pk2(w, w);
        const u64* pr = (const u64*)&src_s[c * 22];
        #pragma unroll
        for (int t = 0; t < 10; t++) ffma2(acc[t], w2, pr[t]);
    }
    #pragma unroll
    for (int t = 0; t < 10; t++) {
        #pragma unroll
        for (int s = 8; s; s >>= 1)
            fadd2(acc[t], __shfl_xor_sync(0xffffffffu, acc[t], s));
    }
    if (g == 0) {
        float* dp = g_wv + (size_t)(n * OUTC + o) * 20;
        #pragma unroll
        for (int t = 0; t < 10; t++) {
            float2 v = upk(acc[t]);
            dp[2 * t] = v.x;
            if (2 * t + 1 < KCL) dp[2 * t + 1] = v.y;
        }
    }
}

// ==================== converters ====================
__global__ __launch_bounds__(256) void conv_feats2(const float* __restrict__ X) {
    const size_t TOT4 = (size_t)NB * CIN * HWD / 4;
    size_t i4 = (size_t)blockIdx.x * 256 + threadIdx.x;
    if (i4 >= TOT4) return;
    size_t row = i4 >> 12;
    int s = (int)(i4 & 4095) * 4;
    int n = (int)(row >> 9), c = (int)(row & 511);
    float4 v = *(const float4*)(X + row * HWD + s);
    __nv_bfloat16 h0, h1, h2, h3, l0, l1, l2, l3;
    split_bf16(v.x, h0, l0); split_bf16(v.y, h1, l1);
    split_bf16(v.z, h2, l2); split_bf16(v.w, h3, l3);
    __nv_bfloat16* hi = g_feats2 + ((size_t)n * 2 * CIN + c) * HWD + s;
    __nv_bfloat16* lo = hi + (size_t)CIN * HWD;
    *(u32*)hi = pack_bf2(h0, h1); *(u32*)(hi + 2) = pack_bf2(h2, h3);
    *(u32*)lo = pack_bf2(l0, l1); *(u32*)(lo + 2) = pack_bf2(l2, l3);
}

__global__ __launch_bounds__(256) void conv_w(const float* __restrict__ W,
                                              __nv_bfloat16* __restrict__ A2,
                                              int MK) {
    int i = blockIdx.x * 256 + threadIdx.x;
    if (i >= MK) return;
    __nv_bfloat16 h, l;
    split_bf16(W[i], h, l);
    A2[i] = h;
    A2[MK + i] = l;
}

// ==================== cp.async 2-stage compensated-bf16 GEMM + CBR ====================
// smem layout per stage (byte offsets from stage base):
//   AsH [128][40]b16 @ 0        (10240 B)
//   AsL [128][40]b16 @ A_PL
//   BsH [32][136]b16 @ 2*A_PL   (8704 B)
//   BsL [32][136]b16 @ 2*A_PL + B_PL
#define A_PL 10240
#define B_PL 8704
#define ST_BYTES (2 * A_PL + 2 * B_PL)    // 37888
#define GEMM_SMEM (2 * ST_BYTES)          // 75776  (2 CTA/SM)

__global__ __launch_bounds__(256, 2) void gemm_cp2(
    const __nv_bfloat16* __restrict__ W2, int K, int nMB,
    const __nv_bfloat16* __restrict__ B0, long sB0, long pl0,
    const __nv_bfloat16* __restrict__ B1, long sB1, long pl1, int Ksplit,
    const float* __restrict__ bias, const float* __restrict__ scale,
    const float* __restrict__ tadd,
    float* __restrict__ Yf, long sYf,
    __nv_bfloat16* __restrict__ Y2, long sY2, long plY)
{
    extern __shared__ __align__(16) char smem[];
    const u32 sb = smem_u32(smem);

    const int n = blockIdx.z;
    const int m0 = (blockIdx.x % nMB) * BM;
    const int s0 = (blockIdx.x / nMB) * BN;

    const int tid = threadIdx.x;
    const int lane = tid & 31, warp = tid >> 5;
    const int wm = warp >> 2, wn = warp & 3;

    const __nv_bfloat16* b0h = B0 + (size_t)n * sB0;
    const __nv_bfloat16* b0l = b0h + pl0;
    const __nv_bfloat16* b1h = B1 + (size_t)n * sB1;
    const __nv_bfloat16* b1l = b1h + pl1;
    const size_t WloOff = (size_t)nMB * BM * K;

    float acc[4][4][4];
    #pragma unroll
    for (int mi = 0; mi < 4; mi++)
        #pragma unroll
        for (int ni = 0; ni < 4; ni++)
            #pragma unroll
            for (int q = 0; q < 4; q++) acc[mi][ni][q] = 0.f;

    const int nT = K / BK;

    // per-thread loader geometry (8 x 16B cp.async per stage)
    // A: ids 0..1023   -> plane, row(0..127), c(0..3)
    // B: ids 1024..2047-> plane, row(0..31),  c(0..15)
    const int idA0 = tid;            // +256*i for i=0..3
    const int idB0 = tid;            // +256*i for i=0..3 (within B block)

    auto load_stage = [&](int t, int buf) {
        const int kt = t * BK;
        const u32 st = sb + buf * ST_BYTES;
        #pragma unroll
        for (int i = 0; i < 4; i++) {
            int id = idA0 + i * 256;              // 0..1023
            int plane = id >> 9, e = id & 511;
            int row = e >> 2, c = e & 3;
            const __nv_bfloat16* src = W2 + (plane ? WloOff : 0)
                + (size_t)(m0 + row) * K + kt + c * 8;
            cp16(st + (plane ? A_PL : 0) + row * 80 + c * 16, src);
        }
        #pragma unroll
        for (int i = 0; i < 4; i++) {
            int id = idB0 + i * 256;              // 0..1023
            int plane = id >> 9, e = id & 511;
            int row = e >> 4, c = e & 15;
            int r = kt + row;
            const __nv_bfloat16* base = (r < Ksplit)
                ? (plane ? b0l : b0h) + (size_t)r * HWD
                : (plane ? b1l : b1h) + (size_t)(r - Ksplit) * HWD;
            cp16(st + 2 * A_PL + (plane ? B_PL : 0) + row * 272 + c * 16,
                 base + s0 + c * 8);
        }
    };

    const u32 aOff = ((wm * 64 + (lane & 15)) * 40 + ((lane >> 4) << 3)) * 2;
    const u32 bOff = ((lane & 15) * 136 + wn * 32 + ((lane >> 4) << 3)) * 2;
    const u32 A_MI = 16 * 40 * 2;
    const u32 B_KS = 16 * 136 * 2;

    load_stage(0, 0);
    CP_COMMIT();

    for (int t = 0; t < nT; t++) {
        CP_WAIT0();
        __syncthreads();
        if (t + 1 < nT) {
            load_stage(t + 1, (t + 1) & 1);
            CP_COMMIT();
        }

        const u32 st = sb + (t & 1) * ST_BYTES;
        const u32 ahA = st + aOff;
        const u32 alA = st + A_PL + aOff;
        const u32 bhA = st + 2 * A_PL + bOff;
        const u32 blA = st + 2 * A_PL + B_PL + bOff;

        #pragma unroll
        for (int ks = 0; ks < 2; ks++) {
            u32 rbh0[4], rbh1[4], rbl0[4], rbl1[4];
            ldsm4t(rbh0, bhA + ks * B_KS);
            ldsm4t(rbh1, bhA + ks * B_KS + 32);
            ldsm4t(rbl0, blA + ks * B_KS);
            ldsm4t(rbl1, blA + ks * B_KS + 32);

            u32 ra[4][4];
            #pragma unroll
            for (int mi = 0; mi < 4; mi++) ldsm4(ra[mi], ahA + mi * A_MI + ks * 32);
            #pragma unroll
            for (int mi = 0; mi < 4; mi++) {
                mma16816(acc[mi][0], ra[mi], &rbh0[0]);
                mma16816(acc[mi][1], ra[mi], &rbh0[2]);
                mma16816(acc[mi][2], ra[mi], &rbh1[0]);
                mma16816(acc[mi][3], ra[mi], &rbh1[2]);
            }
            #pragma unroll
            for (int mi = 0; mi < 4; mi++) {
                mma16816(acc[mi][0], ra[mi], &rbl0[0]);
                mma16816(acc[mi][1], ra[mi], &rbl0[2]);
                mma16816(acc[mi][2], ra[mi], &rbl1[0]);
                mma16816(acc[mi][3], ra[mi], &rbl1[2]);
            }
            #pragma unroll
            for (int mi = 0; mi < 4; mi++) ldsm4(ra[mi], alA + mi * A_MI + ks * 32);
            #pragma unroll
            for (int mi = 0; mi < 4; mi++) {
                mma16816(acc[mi][0], ra[mi], &rbh0[0]);
                mma16816(acc[mi][1], ra[mi], &rbh0[2]);
                mma16816(acc[mi][2], ra[mi], &rbh1[0]);
                mma16816(acc[mi][3], ra[mi], &rbh1[2]);
            }
        }
    }

    // ---- epilogue ----
    const int orow = lane >> 2;
    const int scol = (lane & 3) * 2;
    if (Yf) {
        float* y = Yf + (size_t)n * sYf;
        #pragma unroll
        for (int mi = 0; mi < 4; mi++) {
            const int oA = m0 + wm * 64 + mi * 16 + orow;
            const int oB = oA + 8;
            const float biA = bias[oA], scA = scale[oA], taA = tadd[oA];
            const float biB = bias[oB], scB = scale[oB], taB = tadd[oB];
            #pragma unroll
            for (int ni = 0; ni < 4; ni++) {
                const int s = s0 + wn * 32 + ni * 8 + scol;
                float2 r0 = make_float2(
                    fmaxf((acc[mi][ni][0] + biA) * scA + taA, 0.f),
                    fmaxf((acc[mi][ni][1] + biA) * scA + taA, 0.f));
                float2 r1 = make_float2(
                    fmaxf((acc[mi][ni][2] + biB) * scB + taB, 0.f),
                    fmaxf((acc[mi][ni][3] + biB) * scB + taB, 0.f));
                *(float2*)(y + (size_t)oA * HWD + s) = r0;
                *(float2*)(y + (size_t)oB * HWD + s) = r1;
            }
        }
    } else {
        __nv_bfloat16* yh = Y2 + (size_t)n * sY2;
        __nv_bfloat16* yl = yh + plY;
        #pragma unroll
        for (int mi = 0; mi < 4; mi++) {
            const int oA = m0 + wm * 64 + mi * 16 + orow;
            const int oB = oA + 8;
            const float biA = bias[oA], scA = scale[oA], taA = tadd[oA];
            const float biB = bias[oB], scB = scale[oB], taB = tadd[oB];
            #pragma unroll
            for (int ni = 0; ni < 4; ni++) {
                const int s = s0 + wn * 32 + ni * 8 + scol;
                float vA0 = fmaxf((acc[mi][ni][0] + biA) * scA + taA, 0.f);
                float vA1 = fmaxf((acc[mi][ni][1] + biA) * scA + taA, 0.f);
                float vB0 = fmaxf((acc[mi][ni][2] + biB) * scB + taB, 0.f);
                float vB1 = fmaxf((acc[mi][ni][3] + biB) * scB + taB, 0.f);
                __nv_bfloat16 hA0, lA0, hA1, lA1, hB0, lB0, hB1, lB1;
                split_bf16(vA0, hA0, lA0); split_bf16(vA1, hA1, lA1);
                split_bf16(vB0, hB0, lB0); split_bf16(vB1, hB1, lB1);
                *(u32*)(yh + (size_t)oA * HWD + s) = pack_bf2(hA0, hA1);
                *(u32*)(yl + (size_t)oA * HWD + s) = pack_bf2(lA0, lA1);
                *(u32*)(yh + (size_t)oB * HWD + s) = pack_bf2(hB0, hB1);
                *(u32*)(yl + (size_t)oB * HWD + s) = pack_bf2(lB0, lB1);
            }
        }
    }
}

// ==================== attention + folded f_up (writes up planes) ====================
__global__ __launch_bounds__(256) void attn_up_k(
    const float* __restrict__ bu, const float* __restrict__ su,
    const float* __restrict__ tu)
{
    const int n = blockIdx.z;
    const int oh = blockIdx.y;             // 0 or 1
    __shared__ __align__(8) float kk_s[KC * 20];
    __shared__ __align__(8) float wv_s[256 * 20];
    __shared__ float prm[3 * 256];

    for (int idx = threadIdx.x; idx < KC * 20; idx += 256)
        kk_s[idx] = g_kk[(size_t)n * KC * 20 + idx];
    for (int idx = threadIdx.x; idx < 256 * 20; idx += 256)
        wv_s[idx] = g_wv[((size_t)n * OUTC + oh * 256) * 20 + idx];
    {
        int o = oh * 256 + threadIdx.x;
        prm[threadIdx.x] = bu[o];
        prm[256 + threadIdx.x] = su[o];
        prm[512 + threadIdx.x] = tu[o];
    }
    __syncthreads();

    const int sa = blockIdx.x * 256 + threadIdx.x;
    const float* qn = g_q2 + (size_t)n * KC * HWD;

    u64 lg[10];
    #pragma unroll
    for (int t = 0; t < 10; t++) lg[t] = 0ull;

    #pragma unroll 4
    for (int c = 0; c < KC; c++) {
        float q = qn[(size_t)c * HWD + sa];
        u64 q2 = pk2(q, q);
        const u64* kr = (const u64*)&kk_s[c * 20];
        #pragma unroll
        for (int t = 0; t < 10; t++) ffma2(lg[t], q2, kr[t]);
    }

    float la[20];
    #pragma unroll
    for (int t = 0; t < 10; t++) {
        float2 v = upk(lg[t]); la[2 * t] = v.x; la[2 * t + 1] = v.y;
    }
    const float scl = 0.0625f;
    float m = -3.4e38f;
    #pragma unroll
    for (int k = 0; k < KCL; k++) { la[k] *= scl; m = fmaxf(m, la[k]); }
    float sum = 0.f;
    #pragma unroll
    for (int k = 0; k < KCL; k++) { la[k] = __expf(la[k] - m); sum += la[k]; }
    const float iv = 1.f / sum;
    #pragma unroll
    for (int k = 0; k < KCL; k++) la[k] *= iv;
    la[19] = 0.f;

    u64 sim2[10];
    #pragma unroll
    for (int t = 0; t < 10; t++) sim2[t] = pk2(la[2 * t], la[2 * t + 1]);

    __nv_bfloat16* uph = g_up2 + ((size_t)n * 2 * CIN + oh * 256) * HWD + sa;
    __nv_bfloat16* upl = uph + (size_t)CIN * HWD;

    #pragma unroll 4
    for (int oo = 0; oo < 256; oo++) {
        const u64* vr = (const u64*)&wv_s[oo * 20];
        u64 a = 0ull;
        #pragma unroll
        for (int t = 0; t < 10; t++) ffma2(a, sim2[t], vr[t]);
        float2 v = upk(a);
        float f = fmaxf(((v.x + v.y) + prm[oo]) * prm[256 + oo] + prm[512 + oo], 0.f);
        __nv_bfloat16 h, l;
        split_bf16(f, h, l);
        uph[(size_t)oo * HWD] = h;
        upl[(size_t)oo * HWD] = l;
    }
}

// ==================== host driver ====================
extern "C" void kernel_launch(void* const* d_in, const int* in_sizes, int n_in,
                              void* d_out, int out_size) {
    const float* feats = (const float*)d_in[0];
    const float* probs = (const float*)d_in[1];
    const float* wp1 = (const float*)d_in[2];
    const float* bp1 = (const float*)d_in[3];
    const float* sp1 = (const float*)d_in[4];
    const float* tp1 = (const float*)d_in[5];
    const float* wp2 = (const float*)d_in[6];
    const float* bp2 = (const float*)d_in[7];
    const float* sp2 = (const float*)d_in[8];
    const float* tp2 = (const float*)d_in[9];
    const float* wo1 = (const float*)d_in[10];
    const float* bo1 = (const float*)d_in[11];
    const float* so1 = (const float*)d_in[12];
    const float* to1 = (const float*)d_in[13];
    const float* wo2 = (const float*)d_in[14];
    const float* bo2 = (const float*)d_in[15];
    const float* so2 = (const float*)d_in[16];
    const float* to2 = (const float*)d_in[17];
    const float* wd  = (const float*)d_in[18];
    const float* bd  = (const float*)d_in[19];
    const float* sd  = (const float*)d_in[20];
    const float* td  = (const float*)d_in[21];
    const float* wu  = (const float*)d_in[22];
    const float* bu  = (const float*)d_in[23];
    const float* su  = (const float*)d_in[24];
    const float* tu  = (const float*)d_in[25];
    const float* wf  = (const float*)d_in[26];
    const float* bf  = (const float*)d_in[27];
    const float* sf  = (const float*)d_in[28];
    const float* tf  = (const float*)d_in[29];
    float* out = (float*)d_out;

    void *pproxy, *pt1, *pkk, *pval, *pq2, *pf2, *pq12, *pup2;
    void *pw1, *pw2, *pwf;
    cudaGetSymbolAddress(&pproxy, g_proxy);
    cudaGetSymbolAddress(&pt1, g_t1);
    cudaGetSymbolAddress(&pkk, g_kk);
    cudaGetSymbolAddress(&pval, g_val);
    cudaGetSymbolAddress(&pq2, g_q2);
    cudaGetSymbolAddress(&pf2, g_feats2);
    cudaGetSymbolAddress(&pq12, g_q12);
    cudaGetSymbolAddress(&pup2, g_up2);
    cudaGetSymbolAddress(&pw1, g_wp1_2);
    cudaGetSymbolAddress(&pw2, g_wp2_2);
    cudaGetSymbolAddress(&pwf, g_wf_2);

    cudaFuncSetAttribute(gemm_cp2, cudaFuncAttributeMaxDynamicSharedMemorySize, GEMM_SMEM);

    // converters
    conv_feats2<<<(NB * CIN * HWD / 4 + 255) / 256, 256>>>(feats);
    conv_w<<<(KC * CIN + 255) / 256, 256>>>(wp1, (__nv_bfloat16*)pw1, KC * CIN);
    conv_w<<<(KC * KC + 255) / 256, 256>>>(wp2, (__nv_bfloat16*)pw2, KC * KC);
    conv_w<<<(OUTC * 2 * CIN + 255) / 256, 256>>>(wf, (__nv_bfloat16*)pwf, OUTC * 2 * CIN);

    // softmax + proxy + object branch + Wv
    softmax_k<<<NB * KCL, 256>>>(probs);
    proxy_k<<<dim3(32, NB), 256>>>(feats);
    obj_gemm<<<dim3(16, NB), 256, CIN * 22 * 4>>>(wo1, bo1, so1, to1,
        (const float*)pproxy, (float*)pt1, CIN);
    obj_gemm<<<dim3(16, NB), 256, CIN * 22 * 4>>>(wd, bd, sd, td,
        (const float*)pproxy, (float*)pval, CIN);
    obj_gemm<<<dim3(16, NB), 256, KC * 22 * 4>>>(wo2, bo2, so2, to2,
        (const float*)pt1, (float*)pkk, KC);
    wv_gemm<<<dim3(32, NB), 256>>>(wu);

    // q1 = cbr(wp1 @ feats) -> planes            M=256, K=512
    gemm_cp2<<<dim3((HWD / BN) * (KC / BM), 1, NB), 256, GEMM_SMEM>>>(
        (const __nv_bfloat16*)pw1, CIN, KC / BM,
        (const __nv_bfloat16*)pf2, 2L * CIN * HWD, (long)CIN * HWD,
        (const __nv_bfloat16*)pf2, 2L * CIN * HWD, (long)CIN * HWD, CIN,
        bp1, sp1, tp1,
        nullptr, 0,
        (__nv_bfloat16*)pq12, 2L * KC * HWD, (long)KC * HWD);

    // q2 = cbr(wp2 @ q1) -> fp32                 M=256, K=256
    gemm_cp2<<<dim3((HWD / BN) * (KC / BM), 1, NB), 256, GEMM_SMEM>>>(
        (const __nv_bfloat16*)pw2, KC, KC / BM,
        (const __nv_bfloat16*)pq12, 2L * KC * HWD, (long)KC * HWD,
        (const __nv_bfloat16*)pq12, 2L * KC * HWD, (long)KC * HWD, KC,
        bp2, sp2, tp2,
        (float*)pq2, (long)KC * HWD,
        nullptr, 0, 0);

    // attention + folded f_up -> up planes
    attn_up_k<<<dim3(HWD / 256, 2, NB), 256>>>(bu, su, tu);

    // out = cbr(wf @ cat[up, feats]) -> fp32     M=512, K=1024, Ksplit=512
    gemm_cp2<<<dim3((HWD / BN) * (OUTC / BM), 1, NB), 256, GEMM_SMEM>>>(
        (const __nv_bfloat16*)pwf, 2 * CIN, OUTC / BM,
        (const __nv_bfloat16*)pup2, 2L * CIN * HWD, (long)CIN * HWD,
        (const __nv_bfloat16*)pf2, 2L * CIN * HWD, (long)CIN * HWD, CIN,
        bf, sf, tf,
        out, (long)OUTC * HWD,
        nullptr, 0, 0);
}